// round 12
// baseline (speedup 1.0000x reference)
#include <cuda_runtime.h>
#include <cstdint>

// Hybrid dual-path streaming reduction over 8M points:
//  - 60% of the array is read via LDG.128 (per-thread, interleaved grid-stride)
//  - 40% via cp.async.bulk (TMA) tiles into SMEM, 3-stage mbarrier pipeline
// Both paths run CONCURRENTLY in every CTA to sum the per-SM in-flight
// budgets of the two memory paths.
//   g   = sum_i exp(-0.5*((|p_i - cam|-2)/4)^2) / (4*sqrt(2*pi))
//   cnt = # points strictly inside rotated+translated CCW triangle
// out[0] = 1/(g+eps) + 1/(cnt+eps);  cnt = N - (# outside) via sign bits.

#define GRID     608          // 4 CTAs/SM * 152 SMs
#define THREADS  256
#define STAGES   3
#define TILE_F4  512          // 8 KB tiles
#define TILE_BYTES (TILE_F4 * 16)
#define A_PER_IT 3            // LDG float4 per thread per iteration

__device__ float g_partial_gauss[GRID];
__device__ float g_partial_out[GRID];
__device__ int   g_ticket = 0;

#define GAUSS_NORM 0.09973557010f
#define EPSV 1e-06f
#define KFOLD  0.2123346587f
#define KFOLD2 0.4246693174f

__device__ __forceinline__ float fast_sqrt(float x) {
    float r; asm("sqrt.approx.f32 %0, %1;" : "=f"(r) : "f"(x)); return r;
}
__device__ __forceinline__ float fast_ex2(float x) {
    float r; asm("ex2.approx.f32 %0, %1;" : "=f"(r) : "f"(x)); return r;
}
__device__ __forceinline__ uint32_t s2u(const void* p) {
    uint32_t a;
    asm("{ .reg .u64 t; cvta.to.shared.u64 t, %1; cvt.u32.u64 %0, t; }"
        : "=r"(a) : "l"(p));
    return a;
}
__device__ __forceinline__ void mbar_init(uint32_t a, uint32_t c) {
    asm volatile("mbarrier.init.shared.b64 [%0], %1;" :: "r"(a), "r"(c) : "memory");
}
__device__ __forceinline__ void mbar_arrive(uint32_t a) {
    asm volatile("mbarrier.arrive.shared.b64 _, [%0];" :: "r"(a) : "memory");
}
__device__ __forceinline__ void mbar_expect_tx(uint32_t a, uint32_t bytes) {
    asm volatile("mbarrier.arrive.expect_tx.shared.b64 _, [%0], %1;"
                 :: "r"(a), "r"(bytes) : "memory");
}
__device__ __forceinline__ void mbar_wait(uint32_t a, int parity) {
    asm volatile(
        "{\n\t.reg .pred P;\n"
        "WL_%=:\n\t"
        "mbarrier.try_wait.parity.acquire.cta.shared::cta.b64 P, [%0], %1, 0x989680;\n\t"
        "@P bra WD_%=;\n\t"
        "bra WL_%=;\n"
        "WD_%=:\n\t}"
        :: "r"(a), "r"(parity) : "memory");
}
__device__ __forceinline__ void bulk_copy(uint32_t dst, const void* src,
                                          uint32_t bytes, uint32_t mbar) {
    asm volatile(
        "cp.async.bulk.shared::cluster.global.mbarrier::complete_tx::bytes "
        "[%0], [%1], %2, [%3];"
        :: "r"(dst), "l"(src), "r"(bytes), "r"(mbar) : "memory");
}

struct Geo {
    float cx, cy;
    float a0, b0, d0, a1, b1, d1, a2, b2, d2;
};

__device__ __forceinline__ void body(const float px, const float py,
                                     const Geo& G, float& acc_g, int& acc_out)
{
    float dx = px - G.cx, dy = py - G.cy;
    float d  = fast_sqrt(fmaf(dx, dx, dy * dy));
    float w  = fmaf(d, KFOLD, -KFOLD2);
    acc_g += fast_ex2(w * -w);

    float c0 = fmaf(G.a0, px, fmaf(G.b0, py, G.d0));
    float c1 = fmaf(G.a1, px, fmaf(G.b1, py, G.d1));
    float c2 = fmaf(G.a2, px, fmaf(G.b2, py, G.d2));
    uint32_t u = __float_as_uint(c0) | __float_as_uint(c1) | __float_as_uint(c2);
    acc_out += (int)(u >> 31);
}

__global__ __launch_bounds__(THREADS, 4)
void fused_kernel(const float4* __restrict__ pts4, int n4, int nA, int ntB, int T,
                  const float* __restrict__ cam, int odd_point,
                  const float* __restrict__ pts_scalar,
                  float n_points, float* __restrict__ out)
{
    __shared__ __align__(128) float4 tiles[STAGES][TILE_F4];   // 24 KB
    __shared__ __align__(16)  uint64_t mbars[2 * STAGES];

    const int tid = threadIdx.x;
    const int bid = blockIdx.x;
    const uint32_t mb = s2u(mbars);   // full[s]=mb+s*16, empty[s]=mb+s*16+8

    // ---- uniform geometry setup ----
    Geo G;
    G.cx = cam[0]; G.cy = cam[1];
    const float yaw = cam[2];
    float s, c;
    __sincosf(yaw, &s, &c);
    const float v0x = G.cx,                  v0y = G.cy;
    const float v1x =  2.f*c - 7.f*s + G.cx, v1y =  2.f*s + 7.f*c + G.cy;
    const float v2x = -2.f*c - 7.f*s + G.cx, v2y = -2.f*s + 7.f*c + G.cy;
    {
        float ex = v1x - v0x, ey = v1y - v0y;
        G.a0 = -ey; G.b0 = ex; G.d0 = ey * v0x - ex * v0y;
        ex = v2x - v1x; ey = v2y - v1y;
        G.a1 = -ey; G.b1 = ex; G.d1 = ey * v1x - ex * v1y;
        ex = v0x - v2x; ey = v0y - v2y;
        G.a2 = -ey; G.b2 = ex; G.d2 = ey * v2x - ex * v2y;
    }

    if (tid == 0) {
        #pragma unroll
        for (int st = 0; st < STAGES; st++) {
            mbar_init(mb + st * 16,     1);        // full: TMA expect_tx
            mbar_init(mb + st * 16 + 8, THREADS);  // empty: all consumers
        }
    }
    __syncthreads();

    // prologue: issue first STAGES tiles of stream B
    if (tid == 0) {
        #pragma unroll
        for (int k = 0; k < STAGES; k++) {
            int t = bid + k * GRID;
            if (t < ntB) {
                uint32_t fb = mb + k * 16;
                mbar_expect_tx(fb, TILE_BYTES);
                bulk_copy(s2u(&tiles[k][0]), pts4 + nA + (size_t)t * TILE_F4,
                          TILE_BYTES, fb);
            }
        }
    }

    float ag0 = 0.f, ag1 = 0.f;
    int   aout = 0;

    const int gs = GRID * THREADS;
    int abase = bid * THREADS + tid;    // stream-A cursor (float4 index)

    for (int k = 0; k < T; k++) {
        // ---- stream A: 3 bounds-checked front-batched LDG.128 ----
        float4 qa[A_PER_IT];
        bool   va[A_PER_IT];
        #pragma unroll
        for (int j = 0; j < A_PER_IT; j++) {
            int idx = abase + j * gs;
            va[j] = idx < nA;
            if (va[j]) qa[j] = pts4[idx];
        }
        abase += A_PER_IT * gs;

        // ---- stream B: consume one 8KB TMA tile ----
        const int  t  = bid + k * GRID;
        const bool tv = (t < ntB);
        const int  st = k % STAGES;
        const int  ph = (k / STAGES) & 1;
        float4 qb0, qb1;
        if (tv) {
            mbar_wait(mb + st * 16, ph);
            qb0 = tiles[st][tid];
            qb1 = tiles[st][tid + THREADS];
        }

        // compute A while B's next tiles are in flight
        #pragma unroll
        for (int j = 0; j < A_PER_IT; j++) {
            if (va[j]) {
                body(qa[j].x, qa[j].y, G, ag0, aout);
                body(qa[j].z, qa[j].w, G, ag1, aout);
            }
        }

        if (tv) {
            body(qb0.x, qb0.y, G, ag0, aout);
            body(qb0.z, qb0.w, G, ag1, aout);
            body(qb1.x, qb1.y, G, ag0, aout);
            body(qb1.z, qb1.w, G, ag1, aout);
            mbar_arrive(mb + st * 16 + 8);          // release stage
            if (tid == 0) {
                int tn = bid + (k + STAGES) * GRID;
                if (tn < ntB) {
                    mbar_wait(mb + st * 16 + 8, ph); // stage fully consumed
                    uint32_t fb = mb + st * 16;
                    mbar_expect_tx(fb, TILE_BYTES);
                    bulk_copy(s2u(&tiles[st][0]),
                              pts4 + nA + (size_t)tn * TILE_F4, TILE_BYTES, fb);
                }
            }
        }
    }

    // tail float4s beyond nA + ntB*TILE_F4 (normally empty)
    for (int i = nA + ntB * TILE_F4 + bid * THREADS + tid; i < n4; i += gs) {
        float4 q = pts4[i];
        body(q.x, q.y, G, ag0, aout);
        body(q.z, q.w, G, ag1, aout);
    }
    // lone trailing point if N odd
    if (odd_point && bid == 0 && tid == 0) {
        body(pts_scalar[4 * n4], pts_scalar[4 * n4 + 1], G, ag0, aout);
    }

    float acc_g = (ag0 + ag1) * GAUSS_NORM;
    float acc_o = (float)aout;

    // ---- block reduction (fixed tree -> deterministic) ----
    __shared__ float sg[THREADS];
    __shared__ float so[THREADS];
    sg[tid] = acc_g;
    so[tid] = acc_o;
    __syncthreads();
    #pragma unroll
    for (int off = THREADS / 2; off > 0; off >>= 1) {
        if (tid < off) {
            sg[tid] += sg[tid + off];
            so[tid] += so[tid + off];
        }
        __syncthreads();
    }

    __shared__ bool is_last;
    if (tid == 0) {
        g_partial_gauss[bid] = sg[0];
        g_partial_out[bid]   = so[0];
        __threadfence();
        is_last = (atomicAdd(&g_ticket, 1) == GRID - 1);
    }
    __syncthreads();

    if (is_last) {
        __threadfence();
        float ag = 0.f, ao = 0.f;
        for (int k = tid; k < GRID; k += THREADS) {
            ag += g_partial_gauss[k];
            ao += g_partial_out[k];
        }
        sg[tid] = ag;
        so[tid] = ao;
        __syncthreads();
        #pragma unroll
        for (int off = THREADS / 2; off > 0; off >>= 1) {
            if (tid < off) {
                sg[tid] += sg[tid + off];
                so[tid] += so[tid + off];
            }
            __syncthreads();
        }
        if (tid == 0) {
            float inside = n_points - so[0];
            out[0] = 1.0f / (sg[0] + EPSV) + 1.0f / (inside + EPSV);
            g_ticket = 0;
        }
    }
}

extern "C" void kernel_launch(void* const* d_in, const int* in_sizes, int n_in,
                              void* d_out, int out_size)
{
    const float* points = (const float*)d_in[0];   // [N,2] float32
    const float* cam    = (const float*)d_in[1];   // [3]  float32
    float* out = (float*)d_out;

    int n_floats  = in_sizes[0];          // 2*N
    int n4        = n_floats / 4;         // float4 groups (2 points each)
    int odd_point = ((n_floats / 2) & 1);
    float n_points = (float)(n_floats / 2);

    // 40% of float4s go to the TMA stream (rounded down to whole tiles)
    int ntB = (int)(((long long)n4 * 2 / 5) / TILE_F4);
    int nA  = n4 - ntB * TILE_F4;

    int tilesPerCta = (ntB + GRID - 1) / GRID;
    int aIters = (nA + A_PER_IT * GRID * THREADS - 1) / (A_PER_IT * GRID * THREADS);
    int T = tilesPerCta > aIters ? tilesPerCta : aIters;

    fused_kernel<<<GRID, THREADS>>>((const float4*)points, n4, nA, ntB, T,
                                    cam, odd_point, points, n_points, out);
}

// round 13
// speedup vs baseline: 1.2333x; 1.2333x over previous
#include <cuda_runtime.h>
#include <cstdint>

// Fused single-kernel two-reduction over 8M points:
//   g   = sum_i exp(-0.5*((|p_i - cam|-2)/4)^2) / (4*sqrt(2*pi))
//   cnt = # points strictly inside rotated+translated CCW triangle
// out[0] = 1/(g+eps) + 1/(cnt+eps)
// Count = N - (# outside) via sign-bit OR of the three crosses.
// Finalize via DETERMINISTIC global atomics: int count + 2^40 fixed-point
// gaussian sum (integer adds are exact & order-independent), so the last
// block reads two scalars instead of re-streaming 1216 partials.

#define GRID    608          // 4 CTAs/SM * 152 SMs, one exact wave
#define THREADS 256
#define UNROLL  8

__device__ unsigned long long g_gauss_fx = 0ull;  // 2^40 fixed-point gaussian sum
__device__ int                g_out_cnt  = 0;     // outside-count
__device__ int                g_ticket   = 0;     // all reset by last block

#define GAUSS_NORM 0.09973557010f   // 1 / (4 * sqrt(2*pi))
#define EPSV 1e-06f
// exp(-0.5*((d-2)/4)^2) = ex2(-(K*d - 2K)^2), K = sqrt(0.5*log2(e))/4
#define KFOLD  0.2123346587f
#define KFOLD2 0.4246693174f        // 2*K
#define FXSCALE 1099511627776.0     // 2^40

__device__ __forceinline__ float fast_sqrt(float x) {
    float r; asm("sqrt.approx.f32 %0, %1;" : "=f"(r) : "f"(x)); return r;
}
__device__ __forceinline__ float fast_ex2(float x) {
    float r; asm("ex2.approx.f32 %0, %1;" : "=f"(r) : "f"(x)); return r;
}

struct Geo {
    float cx, cy;
    float a0, b0, d0, a1, b1, d1, a2, b2, d2;  // cross_k(p) = a*px + b*py + d
};

__device__ __forceinline__ void body(const float px, const float py,
                                     const Geo& G, float& acc_g, int& acc_out)
{
    // gaussian
    float dx = px - G.cx, dy = py - G.cy;
    float d  = fast_sqrt(fmaf(dx, dx, dy * dy));
    float w  = fmaf(d, KFOLD, -KFOLD2);          // K*(d-2)
    acc_g += fast_ex2(w * -w);                   // ex2(-(K(d-2))^2)

    // CCW triangle => inside <=> all crosses > 0; count OUTSIDE via sign bits
    float c0 = fmaf(G.a0, px, fmaf(G.b0, py, G.d0));
    float c1 = fmaf(G.a1, px, fmaf(G.b1, py, G.d1));
    float c2 = fmaf(G.a2, px, fmaf(G.b2, py, G.d2));
    uint32_t u = __float_as_uint(c0) | __float_as_uint(c1) | __float_as_uint(c2);
    acc_out += (int)(u >> 31);
}

__global__ __launch_bounds__(THREADS, 4)
void fused_kernel(const float4* __restrict__ pts4, int n4,
                  const float* __restrict__ cam, int odd_point,
                  const float* __restrict__ pts_scalar,
                  float n_points,
                  float* __restrict__ out)
{
    // ---- uniform geometry setup ----
    Geo G;
    G.cx = cam[0]; G.cy = cam[1];
    const float yaw = cam[2];
    float s, c;
    __sincosf(yaw, &s, &c);
    // POLY {(0,0),(2,7),(-2,7)} is CCW; rotation preserves orientation,
    // so all-negative is impossible (c0+c1+c2 = 2*area > 0).
    const float v0x = G.cx,                      v0y = G.cy;
    const float v1x =  2.f*c - 7.f*s + G.cx,     v1y =  2.f*s + 7.f*c + G.cy;
    const float v2x = -2.f*c - 7.f*s + G.cx,     v2y = -2.f*s + 7.f*c + G.cy;
    {
        float ex = v1x - v0x, ey = v1y - v0y;
        G.a0 = -ey; G.b0 = ex; G.d0 = ey * v0x - ex * v0y;
        ex = v2x - v1x; ey = v2y - v1y;
        G.a1 = -ey; G.b1 = ex; G.d1 = ey * v1x - ex * v1y;
        ex = v0x - v2x; ey = v0y - v2y;
        G.a2 = -ey; G.b2 = ex; G.d2 = ey * v2x - ex * v2y;
    }

    float acc_g0 = 0.f, acc_g1 = 0.f;
    int   acc_out = 0;

    const int stride  = GRID * THREADS;
    const int tid0    = blockIdx.x * THREADS + threadIdx.x;
    const int strideU = UNROLL * stride;

    int i = tid0;
    for (; i + (UNROLL - 1) * stride < n4; i += strideU) {
        float4 q[UNROLL];
        #pragma unroll
        for (int u = 0; u < UNROLL; u++) q[u] = pts4[i + u * stride];
        #pragma unroll
        for (int u = 0; u < UNROLL; u++) {
            body(q[u].x, q[u].y, G, acc_g0, acc_out);
            body(q[u].z, q[u].w, G, acc_g1, acc_out);
        }
    }
    for (; i < n4; i += stride) {
        float4 q = pts4[i];
        body(q.x, q.y, G, acc_g0, acc_out);
        body(q.z, q.w, G, acc_g1, acc_out);
    }
    // lone trailing point if N odd
    if (odd_point && blockIdx.x == 0 && threadIdx.x == 0) {
        body(pts_scalar[4 * n4], pts_scalar[4 * n4 + 1], G, acc_g0, acc_out);
    }

    float acc_g = (acc_g0 + acc_g1) * GAUSS_NORM;
    float acc_o = (float)acc_out;

    // ---- block reduction (fixed tree -> deterministic) ----
    __shared__ float sg[THREADS];
    __shared__ float so[THREADS];
    sg[threadIdx.x] = acc_g;
    so[threadIdx.x] = acc_o;
    __syncthreads();
    #pragma unroll
    for (int off = THREADS / 2; off > 0; off >>= 1) {
        if (threadIdx.x < off) {
            sg[threadIdx.x] += sg[threadIdx.x + off];
            so[threadIdx.x] += so[threadIdx.x + off];
        }
        __syncthreads();
    }

    // ---- global reduction via deterministic integer atomics ----
    if (threadIdx.x == 0) {
        // 2^40 fixed point: exact integer adds, order-independent
        unsigned long long fx =
            (unsigned long long)__double2ll_rn((double)sg[0] * FXSCALE);
        atomicAdd(&g_gauss_fx, fx);
        atomicAdd(&g_out_cnt, (int)so[0]);
        __threadfence();
        int t = atomicAdd(&g_ticket, 1);
        if (t == GRID - 1) {
            __threadfence();
            double gsum = (double)g_gauss_fx * (1.0 / FXSCALE);
            float  inside = n_points - (float)g_out_cnt;
            out[0] = 1.0f / ((float)gsum + EPSV) + 1.0f / (inside + EPSV);
            // re-arm for next graph replay
            g_gauss_fx = 0ull;
            g_out_cnt  = 0;
            g_ticket   = 0;
        }
    }
}

extern "C" void kernel_launch(void* const* d_in, const int* in_sizes, int n_in,
                              void* d_out, int out_size)
{
    const float* points = (const float*)d_in[0];   // [N,2] float32
    const float* cam    = (const float*)d_in[1];   // [3]  float32
    float* out = (float*)d_out;

    int n_floats  = in_sizes[0];          // 2*N
    int n4        = n_floats / 4;         // float4 groups (2 points each)
    int odd_point = ((n_floats / 2) & 1); // lone trailing point if N odd
    float n_points = (float)(n_floats / 2);

    fused_kernel<<<GRID, THREADS>>>((const float4*)points, n4, cam,
                                    odd_point, points, n_points, out);
}

// round 14
// speedup vs baseline: 1.2759x; 1.0345x over previous
#include <cuda_runtime.h>
#include <cstdint>

// Fused single-kernel two-reduction over 8M points:
//   g   = sum_i exp(-0.5*((|p_i - cam|-2)/4)^2) / (4*sqrt(2*pi))
//   cnt = # points strictly inside rotated+translated CCW triangle
// out[0] = 1/(g+eps) + 1/(cnt+eps)
// Count = N - (# outside) via sign-bit OR of the three crosses.
// NEW: software L2 prefetch 2 outer iterations ahead so the demand
// LDG.128s hit L2 (~240cyc) instead of DRAM (~577cyc + queue).

#define GRID    608          // 4 CTAs/SM * 152 SMs, one exact wave
#define THREADS 256
#define UNROLL  8
#define PFDIST  2            // prefetch distance in outer iterations

__device__ float g_partial_gauss[GRID];
__device__ float g_partial_out[GRID];
__device__ int   g_ticket = 0;   // reset by finalizing block each call

#define GAUSS_NORM 0.09973557010f   // 1 / (4 * sqrt(2*pi))
#define EPSV 1e-06f
// exp(-0.5*((d-2)/4)^2) = ex2(-(K*d - 2K)^2), K = sqrt(0.5*log2(e))/4
#define KFOLD  0.2123346587f
#define KFOLD2 0.4246693174f        // 2*K

__device__ __forceinline__ float fast_sqrt(float x) {
    float r; asm("sqrt.approx.f32 %0, %1;" : "=f"(r) : "f"(x)); return r;
}
__device__ __forceinline__ float fast_ex2(float x) {
    float r; asm("ex2.approx.f32 %0, %1;" : "=f"(r) : "f"(x)); return r;
}
__device__ __forceinline__ void prefetch_l2(const void* p) {
    asm volatile("prefetch.global.L2 [%0];" :: "l"(p));
}

struct Geo {
    float cx, cy;
    float a0, b0, d0, a1, b1, d1, a2, b2, d2;  // cross_k(p) = a*px + b*py + d
};

__device__ __forceinline__ void body(const float px, const float py,
                                     const Geo& G, float& acc_g, int& acc_out)
{
    // gaussian
    float dx = px - G.cx, dy = py - G.cy;
    float d  = fast_sqrt(fmaf(dx, dx, dy * dy));
    float w  = fmaf(d, KFOLD, -KFOLD2);          // K*(d-2)
    acc_g += fast_ex2(w * -w);                   // ex2(-(K(d-2))^2)

    // CCW triangle => inside <=> all crosses > 0; count OUTSIDE via sign bits
    float c0 = fmaf(G.a0, px, fmaf(G.b0, py, G.d0));
    float c1 = fmaf(G.a1, px, fmaf(G.b1, py, G.d1));
    float c2 = fmaf(G.a2, px, fmaf(G.b2, py, G.d2));
    uint32_t u = __float_as_uint(c0) | __float_as_uint(c1) | __float_as_uint(c2);
    acc_out += (int)(u >> 31);
}

__global__ __launch_bounds__(THREADS, 4)
void fused_kernel(const float4* __restrict__ pts4, int n4,
                  const float* __restrict__ cam, int odd_point,
                  const float* __restrict__ pts_scalar,
                  float n_points,
                  float* __restrict__ out)
{
    // ---- uniform geometry setup ----
    Geo G;
    G.cx = cam[0]; G.cy = cam[1];
    const float yaw = cam[2];
    float s, c;
    __sincosf(yaw, &s, &c);
    // POLY {(0,0),(2,7),(-2,7)} is CCW; rotation preserves orientation,
    // so all-negative is impossible (c0+c1+c2 = 2*area > 0).
    const float v0x = G.cx,                      v0y = G.cy;
    const float v1x =  2.f*c - 7.f*s + G.cx,     v1y =  2.f*s + 7.f*c + G.cy;
    const float v2x = -2.f*c - 7.f*s + G.cx,     v2y = -2.f*s + 7.f*c + G.cy;
    {
        float ex = v1x - v0x, ey = v1y - v0y;
        G.a0 = -ey; G.b0 = ex; G.d0 = ey * v0x - ex * v0y;
        ex = v2x - v1x; ey = v2y - v1y;
        G.a1 = -ey; G.b1 = ex; G.d1 = ey * v1x - ex * v1y;
        ex = v0x - v2x; ey = v0y - v2y;
        G.a2 = -ey; G.b2 = ex; G.d2 = ey * v2x - ex * v2y;
    }

    float acc_g0 = 0.f, acc_g1 = 0.f;
    int   acc_out = 0;

    const int stride  = GRID * THREADS;
    const int tid0    = blockIdx.x * THREADS + threadIdx.x;
    const int strideU = UNROLL * stride;
    const bool pf_lead = ((threadIdx.x & 7) == 0);   // 1 prefetch per 128B line

    int i = tid0;
    for (; i + (UNROLL - 1) * stride < n4; i += strideU) {
        // prefetch the chunk PFDIST outer iterations ahead into L2
        int ip = i + PFDIST * strideU;
        if (pf_lead && ip + (UNROLL - 1) * stride < n4) {
            #pragma unroll
            for (int u = 0; u < UNROLL; u++)
                prefetch_l2(pts4 + ip + u * stride);
        }

        float4 q[UNROLL];
        #pragma unroll
        for (int u = 0; u < UNROLL; u++) q[u] = pts4[i + u * stride];
        #pragma unroll
        for (int u = 0; u < UNROLL; u++) {
            body(q[u].x, q[u].y, G, acc_g0, acc_out);
            body(q[u].z, q[u].w, G, acc_g1, acc_out);
        }
    }
    for (; i < n4; i += stride) {
        float4 q = pts4[i];
        body(q.x, q.y, G, acc_g0, acc_out);
        body(q.z, q.w, G, acc_g1, acc_out);
    }
    // lone trailing point if N odd
    if (odd_point && blockIdx.x == 0 && threadIdx.x == 0) {
        body(pts_scalar[4 * n4], pts_scalar[4 * n4 + 1], G, acc_g0, acc_out);
    }

    float acc_g = (acc_g0 + acc_g1) * GAUSS_NORM;
    float acc_o = (float)acc_out;

    // ---- block reduction (fixed tree -> deterministic) ----
    __shared__ float sg[THREADS];
    __shared__ float so[THREADS];
    sg[threadIdx.x] = acc_g;
    so[threadIdx.x] = acc_o;
    __syncthreads();
    #pragma unroll
    for (int off = THREADS / 2; off > 0; off >>= 1) {
        if (threadIdx.x < off) {
            sg[threadIdx.x] += sg[threadIdx.x + off];
            so[threadIdx.x] += so[threadIdx.x + off];
        }
        __syncthreads();
    }

    __shared__ bool is_last;
    if (threadIdx.x == 0) {
        g_partial_gauss[blockIdx.x] = sg[0];
        g_partial_out[blockIdx.x]   = so[0];
        __threadfence();
        is_last = (atomicAdd(&g_ticket, 1) == GRID - 1);
    }
    __syncthreads();

    if (is_last) {
        __threadfence();
        float ag = 0.f, ao = 0.f;
        for (int k = threadIdx.x; k < GRID; k += THREADS) {
            ag += g_partial_gauss[k];
            ao += g_partial_out[k];
        }
        sg[threadIdx.x] = ag;
        so[threadIdx.x] = ao;
        __syncthreads();
        #pragma unroll
        for (int off = THREADS / 2; off > 0; off >>= 1) {
            if (threadIdx.x < off) {
                sg[threadIdx.x] += sg[threadIdx.x + off];
                so[threadIdx.x] += so[threadIdx.x + off];
            }
            __syncthreads();
        }
        if (threadIdx.x == 0) {
            float inside = n_points - so[0];
            out[0] = 1.0f / (sg[0] + EPSV) + 1.0f / (inside + EPSV);
            g_ticket = 0;   // re-arm for graph replay
        }
    }
}

extern "C" void kernel_launch(void* const* d_in, const int* in_sizes, int n_in,
                              void* d_out, int out_size)
{
    const float* points = (const float*)d_in[0];   // [N,2] float32
    const float* cam    = (const float*)d_in[1];   // [3]  float32
    float* out = (float*)d_out;

    int n_floats  = in_sizes[0];          // 2*N
    int n4        = n_floats / 4;         // float4 groups (2 points each)
    int odd_point = ((n_floats / 2) & 1); // lone trailing point if N odd
    float n_points = (float)(n_floats / 2);

    fused_kernel<<<GRID, THREADS>>>((const float4*)points, n4, cam,
                                    odd_point, points, n_points, out);
}